// round 4
// baseline (speedup 1.0000x reference)
#include <cuda_runtime.h>
#include <cstdint>

// Problem constants
#define B_    64
#define CIN_  64
#define T_    4096
#define F_    128
#define K_    64
#define TOUT_ 4033          // T - K + 1
#define TILE_ 192           // conv outputs per CTA tile
#define NT_   22            // ceil(TOUT_/TILE_)

#define YSTR_  260          // y row stride (floats): 4(f+6s) mod 32 distinct per phase
#define SPSTR_ 68           // spatT row stride
#define CWSTR_ 132          // duplicated conv-w row stride (128 used)

// smem layout (floats)
#define OFF_Y    0                        // 64*260 = 16640
#define OFF_U    (64*YSTR_)               // union buf: max(64*68, 64*132) = 8448
#define OFF_SSQ  (OFF_U + 8448)           // 256
#define OFF_INV  (OFF_SSQ + 256)          // 208
#define SMEM_FLOATS (OFF_INV + 208)       // 25552 floats = 102208 B -> 2 CTAs/SM

__device__ float g_wf[F_];
__device__ float g_bias_sum;
__device__ float g_partial[B_ * NT_];

// ---------------------------------------------------------------------------
// Packed f32x2 helpers (SASS FFMA2 — only reachable via PTX)
// ---------------------------------------------------------------------------
__device__ __forceinline__ float2 ffma2(float2 a, float2 b, float2 c) {
    union U { float2 f; unsigned long long u; };
    U ua{a}, ub{b}, uc{c}, ur;
    asm("fma.rn.f32x2 %0, %1, %2, %3;" : "=l"(ur.u) : "l"(ua.u), "l"(ub.u), "l"(uc.u));
    return ur.f;
}

// ---------------------------------------------------------------------------
// Setup: per-filter combined weight factor + bias sum
// ---------------------------------------------------------------------------
__global__ void setup_kernel(const float* __restrict__ conv_w,
                             const float* __restrict__ spat_w,
                             const float* __restrict__ weight,
                             const float* __restrict__ bias) {
    int f = threadIdx.x;  // 128 threads
    float sc = 0.f, ss = 0.f;
    #pragma unroll 8
    for (int k = 0; k < K_; k++) { float v = conv_w[f * K_ + k]; sc += v * v; }
    #pragma unroll 8
    for (int c = 0; c < CIN_; c++) { float v = spat_w[f * CIN_ + c]; ss += v * v; }
    float norm_w = sqrtf(sc) * sqrtf(ss);
    // scale = sqrt(CIN*K) = 64 exactly; fold 1/Tout for the mean
    g_wf[f] = weight[f] * 64.0f / (norm_w * (float)TOUT_);

    __shared__ float sb[F_];
    sb[f] = bias[f];
    __syncthreads();
    for (int s = F_ / 2; s > 0; s >>= 1) {
        if (f < s) sb[f] += sb[f + s];
        __syncthreads();
    }
    if (f == 0) g_bias_sum = sb[0];
}

// ---------------------------------------------------------------------------
// Main fused kernel: one CTA per (t-tile, batch)
// ---------------------------------------------------------------------------
__global__ __launch_bounds__(256, 2)
void main_kernel(const float* __restrict__ x,
                 const float* __restrict__ conv_w,
                 const float* __restrict__ spat_w) {
    extern __shared__ float sm[];
    float* y_s  = sm + OFF_Y;     // [64][YSTR_]
    float* un   = sm + OFF_U;     // spatT [64c][SPSTR_] / cwdup [64f][CWSTR_]
    float* ssq  = sm + OFF_SSQ;   // [256]
    float* invn = sm + OFF_INV;   // [192+pad]

    const int tid  = threadIdx.x;
    const int b    = blockIdx.y;
    const int tile = blockIdx.x;
    const int t0g  = tile * TILE_;

    const int warp = tid >> 5;
    const int lane = tid & 31;

    const float* xb = x + (size_t)b * CIN_ * T_;

    // ---- channel-energy ssq[t] (from global, coalesced) ----
    {
        int t = t0g + tid;
        float s = 0.f;
        if (t < T_) {
            #pragma unroll 8
            for (int c = 0; c < CIN_; c++) { float v = xb[c * T_ + t]; s += v * v; }
        }
        ssq[tid] = s;
    }
    __syncthreads();
    if (tid < TILE_) {
        float s = 0.f;
        #pragma unroll 8
        for (int k = 0; k < K_; k++) s += ssq[tid + k];
        invn[tid] = ((t0g + tid) < TOUT_ && s > 0.f) ? rsqrtf(s) : 0.f;
    }

    // spatial mapping: warp -> 8 filters (fo..fo+7), lane -> t quads {4L, 4L+128}
    const int fo = 8 * warp;
    const int tA = 4 * lane;
    const bool ok0 = (t0g + tA + 3)       < T_;
    const bool ok1 = (t0g + tA + 128 + 3) < T_;
    const float4 z4 = make_float4(0.f, 0.f, 0.f, 0.f);
    const float* xg = xb + t0g;

    // temporal mapping: thread -> (filter f_loc, slot of 24 t) x 2 passes
    const int f_loc = tid >> 2;          // 0..63
    const int slot  = tid & 3;

    float2 psum2 = make_float2(0.f, 0.f);

    for (int g = 0; g < 2; g++) {
        // ---- stage spatT: un[c*SPSTR_ + f] = spat_w[(64g+f)*64 + c] ----
        __syncthreads();
        #pragma unroll
        for (int r = 0; r < 16; r++) {
            int idx = r * 256 + tid;
            int f = idx >> 6, c = idx & 63;
            un[c * SPSTR_ + f] = spat_w[(64 * g + f) * CIN_ + c];
        }
        __syncthreads();

        // ---- spatial GEMM: y[f][t] = sum_c spat[f,c] x[c][t]  (8f x 8t / thread)
        float2 acc[8][4];
        #pragma unroll
        for (int fi = 0; fi < 8; fi++)
            #pragma unroll
            for (int j = 0; j < 4; j++) acc[fi][j] = make_float2(0.f, 0.f);

        #pragma unroll 4
        for (int c = 0; c < CIN_; c++) {
            float4 xa = ok0 ? *(const float4*)(xg + c * T_ + tA)       : z4;
            float4 xc = ok1 ? *(const float4*)(xg + c * T_ + tA + 128) : z4;
            float4 wA = *(const float4*)(un + c * SPSTR_ + fo);
            float4 wB = *(const float4*)(un + c * SPSTR_ + fo + 4);
            float2 p0 = make_float2(xa.x, xa.y), p1 = make_float2(xa.z, xa.w);
            float2 p2 = make_float2(xc.x, xc.y), p3 = make_float2(xc.z, xc.w);
            float wv[8] = {wA.x, wA.y, wA.z, wA.w, wB.x, wB.y, wB.z, wB.w};
            #pragma unroll
            for (int fi = 0; fi < 8; fi++) {
                float2 s = make_float2(wv[fi], wv[fi]);
                acc[fi][0] = ffma2(s, p0, acc[fi][0]);
                acc[fi][1] = ffma2(s, p1, acc[fi][1]);
                acc[fi][2] = ffma2(s, p2, acc[fi][2]);
                acc[fi][3] = ffma2(s, p3, acc[fi][3]);
            }
        }
        #pragma unroll
        for (int fi = 0; fi < 8; fi++) {
            float* yr = y_s + (fo + fi) * YSTR_;
            *(float4*)(yr + tA) =
                make_float4(acc[fi][0].x, acc[fi][0].y, acc[fi][1].x, acc[fi][1].y);
            *(float4*)(yr + tA + 128) =
                make_float4(acc[fi][2].x, acc[fi][2].y, acc[fi][3].x, acc[fi][3].y);
        }
        __syncthreads();

        // ---- stage duplicated conv weights: un[f*CWSTR_ + 2k] = (w,w) ----
        #pragma unroll
        for (int r = 0; r < 16; r++) {
            int idx = r * 256 + tid;
            int f = idx >> 6, k = idx & 63;
            float v = conv_w[(64 * g + f) * K_ + k];
            *(float2*)(un + f * CWSTR_ + 2 * k) = make_float2(v, v);
        }
        __syncthreads();

        // ---- temporal conv + |.|*invn accumulate ----
        const float* yrow = y_s + f_loc * YSTR_;
        const float* cwd  = un  + f_loc * CWSTR_;
        const float  wf   = g_wf[64 * g + f_loc];
        const float2 wfs  = make_float2(wf, wf);

        for (int pass = 0; pass < 2; pass++) {
            const int t0 = 96 * pass + 24 * slot;

            float2 tacc[12];
            #pragma unroll
            for (int i = 0; i < 12; i++) tacc[i] = make_float2(0.f, 0.f);

            float2 wp[16];   // circular window: y[t0 + 4q .. t0 + 4q + 31]
            #pragma unroll
            for (int j = 0; j < 8; j++) {
                float4 v = *(const float4*)(yrow + t0 + 4 * j);
                wp[2 * j]     = make_float2(v.x, v.y);
                wp[2 * j + 1] = make_float2(v.z, v.w);
            }

            for (int qq = 0; qq < 2; qq++) {
                #pragma unroll
                for (int u = 0; u < 8; u++) {
                    const int q = 8 * qq + u;
                    const int r = (2 * u) & 15;     // == (2q) & 15
                    float4 cw0 = *(const float4*)(cwd + 8 * q);
                    float4 cw1 = *(const float4*)(cwd + 8 * q + 4);
                    float2 s0 = make_float2(cw0.x, cw0.y);
                    float2 s1 = make_float2(cw0.z, cw0.w);
                    float2 s2 = make_float2(cw1.x, cw1.y);
                    float2 s3 = make_float2(cw1.z, cw1.w);

                    float4 nv = z4;
                    if (q < 14) nv = *(const float4*)(yrow + t0 + 4 * q + 32);

                    // odd-offset window pairs: od[j] = (y[t0+4q+2j+1], y[t0+4q+2j+2])
                    float2 od[13];
                    #pragma unroll
                    for (int j = 0; j < 13; j++)
                        od[j] = make_float2(wp[(r + j) & 15].y, wp[(r + j + 1) & 15].x);

                    #pragma unroll
                    for (int i = 0; i < 12; i++) {
                        tacc[i] = ffma2(s0, wp[(r + i) & 15],     tacc[i]);
                        tacc[i] = ffma2(s1, od[i],                tacc[i]);
                        tacc[i] = ffma2(s2, wp[(r + i + 1) & 15], tacc[i]);
                        tacc[i] = ffma2(s3, od[i + 1],            tacc[i]);
                    }

                    if (q < 14) {
                        wp[r]            = make_float2(nv.x, nv.y);
                        wp[(r + 1) & 15] = make_float2(nv.z, nv.w);
                    }
                }
            }

            // epilogue: psum += wf * |conved| * invn   (invn==0 kills t >= TOUT)
            #pragma unroll
            for (int i = 0; i < 12; i++) {
                float2 iv = *(const float2*)(invn + t0 + 2 * i);
                float2 a  = make_float2(fabsf(tacc[i].x) * iv.x,
                                        fabsf(tacc[i].y) * iv.y);
                psum2 = ffma2(wfs, a, psum2);
            }
        }
    }

    // ---- block reduce -> partial ----
    float psum = psum2.x + psum2.y;
    #pragma unroll
    for (int o = 16; o > 0; o >>= 1)
        psum += __shfl_xor_sync(0xffffffffu, psum, o);
    __syncthreads();               // ssq no longer needed; reuse as scratch
    if (lane == 0) ssq[warp] = psum;
    __syncthreads();
    if (tid == 0) {
        float s = 0.f;
        #pragma unroll
        for (int i = 0; i < 8; i++) s += ssq[i];
        g_partial[b * NT_ + tile] = s;
    }
}

// ---------------------------------------------------------------------------
// Final reduction: out[b] = bias_sum + sum over tiles
// ---------------------------------------------------------------------------
__global__ void finish_kernel(float* __restrict__ out) {
    int b = threadIdx.x;  // 64 threads
    float s = g_bias_sum;
    #pragma unroll
    for (int i = 0; i < NT_; i++) s += g_partial[b * NT_ + i];
    out[b] = s;
}

// ---------------------------------------------------------------------------
extern "C" void kernel_launch(void* const* d_in, const int* in_sizes, int n_in,
                              void* d_out, int out_size) {
    const float* x      = (const float*)d_in[0];  // [64,64,4096]
    const float* conv_w = (const float*)d_in[1];  // [128,64]
    const float* spat_w = (const float*)d_in[2];  // [128,64]
    const float* weight = (const float*)d_in[3];  // [128]
    const float* bias   = (const float*)d_in[4];  // [128]
    float* out = (float*)d_out;                   // [64]

    cudaFuncSetAttribute(main_kernel,
                         cudaFuncAttributeMaxDynamicSharedMemorySize,
                         SMEM_FLOATS * sizeof(float));

    setup_kernel<<<1, 128>>>(conv_w, spat_w, weight, bias);
    dim3 grid(NT_, B_);
    main_kernel<<<grid, 256, SMEM_FLOATS * sizeof(float)>>>(x, conv_w, spat_w);
    finish_kernel<<<1, 64>>>(out);
}

// round 5
// speedup vs baseline: 1.0058x; 1.0058x over previous
#include <cuda_runtime.h>
#include <cstdint>

// Problem constants
#define B_    64
#define CIN_  64
#define T_    4096
#define F_    128
#define K_    64
#define TOUT_ 4033          // T - K + 1
#define TILE_ 192           // conv outputs per CTA tile
#define NT_   22            // ceil(TOUT_/TILE_)
#define NCTA_ (NT_ * B_)    // 1408

#define YIL2S 261           // yil row stride in float2 (odd -> conflict-free LDS.64)
#define CW2S  65            // cwil row stride in float2 (odd)
#define SPS   72            // spatT row stride (floats)

// smem layout (floats)
#define OFF_YIL  0                       // 32 * 261 * 2 = 16704
#define OFF_U    16704                   // max(spatT 64*72=4608, cwil 32*65*2=4160)
#define OFF_SSQ  (OFF_U + 4608)          // 256
#define OFF_INV  (OFF_SSQ + 256)         // 192 (+pad)
#define SMEM_FLOATS (OFF_INV + 208)      // 21776 floats = 87104 B -> 2 CTAs/SM

__device__ float    g_acc[B_ * F_];      // deferred per-(b,f) sums (zero-init)
__device__ unsigned g_count;             // CTA completion counter (zero-init)

// ---------------------------------------------------------------------------
// Packed f32x2 FMA (SASS FFMA2 — only reachable via PTX)
// ---------------------------------------------------------------------------
__device__ __forceinline__ float2 ffma2(float2 a, float2 b, float2 c) {
    union U { float2 f; unsigned long long u; };
    U ua{a}, ub{b}, uc{c}, ur;
    asm("fma.rn.f32x2 %0, %1, %2, %3;" : "=l"(ur.u) : "l"(ua.u), "l"(ub.u), "l"(uc.u));
    return ur.f;
}

// ---------------------------------------------------------------------------
// Single fused kernel: one CTA per (t-tile, batch); last CTA finishes.
// ---------------------------------------------------------------------------
__global__ __launch_bounds__(256, 2)
void main_kernel(const float* __restrict__ x,
                 const float* __restrict__ conv_w,
                 const float* __restrict__ spat_w,
                 const float* __restrict__ weight,
                 const float* __restrict__ bias,
                 float* __restrict__ out) {
    extern __shared__ float sm[];
    float2* yil2 = (float2*)(sm + OFF_YIL);   // [32 pairs][YIL2S f2]
    float*  un   = sm + OFF_U;                // spatT / cwil union
    float2* cw2  = (float2*)(sm + OFF_U);
    float*  ssq  = sm + OFF_SSQ;              // [256]
    float*  invn = sm + OFF_INV;              // [192]
    __shared__ unsigned sflag;

    const int tid  = threadIdx.x;
    const int b    = blockIdx.y;
    const int tile = blockIdx.x;
    const int t0g  = tile * TILE_;
    const int warp = tid >> 5;
    const int lane = tid & 31;

    const float* xb = x + (size_t)b * CIN_ * T_;

    // ---- channel-energy ssq[t] then sliding inverse norm ----
    {
        int t = t0g + tid;
        float s = 0.f;
        if (t < T_) {
            #pragma unroll 8
            for (int c = 0; c < CIN_; c++) { float v = xb[c * T_ + t]; s += v * v; }
        }
        ssq[tid] = s;
    }
    __syncthreads();
    if (tid < TILE_) {
        float s = 0.f;
        #pragma unroll 8
        for (int k = 0; k < K_; k++) s += ssq[tid + k];
        invn[tid] = ((t0g + tid) < TOUT_ && s > 0.f) ? rsqrtf(s) : 0.f;
    }

    // spatial mapping: warp -> 8 filters, lane -> t quads {4L, 4L+128}
    const int fo = 8 * warp;
    const int tA = 4 * lane;
    const bool ok0 = (t0g + tA + 3)   < T_;   // quads fully in or fully out
    const bool ok1 = (t0g + tA + 131) < T_;
    const float4 z4 = make_float4(0.f, 0.f, 0.f, 0.f);
    const float* xg = xb + t0g;

    float accE[B_ == 0 ? 1 : 1];  // (silence unused warnings pattern; unused)

    for (int g = 0; g < 2; g++) {
        const int gbase = 64 * g;

        // ---- stage spatT: un[c*SPS + f] = spat_w[(gbase+f)*64 + c] ----
        __syncthreads();
        #pragma unroll
        for (int r = 0; r < 16; r++) {
            int idx = r * 256 + tid;
            int f = idx >> 6, c = idx & 63;
            un[c * SPS + f] = spat_w[(gbase + f) * CIN_ + c];
        }
        __syncthreads();

        // ---- spatial GEMM: 8 filters x 8 t per thread, x from global (L1) ----
        float2 acc[8][4];
        #pragma unroll
        for (int fi = 0; fi < 8; fi++)
            #pragma unroll
            for (int j = 0; j < 4; j++) acc[fi][j] = make_float2(0.f, 0.f);

        #pragma unroll 2
        for (int c = 0; c < CIN_; c++) {
            float4 xa = ok0 ? *(const float4*)(xg + c * T_ + tA)       : z4;
            float4 xc = ok1 ? *(const float4*)(xg + c * T_ + tA + 128) : z4;
            float4 wA = *(const float4*)(un + c * SPS + fo);
            float4 wB = *(const float4*)(un + c * SPS + fo + 4);
            float2 p0 = make_float2(xa.x, xa.y), p1 = make_float2(xa.z, xa.w);
            float2 p2 = make_float2(xc.x, xc.y), p3 = make_float2(xc.z, xc.w);
            float wv[8] = {wA.x, wA.y, wA.z, wA.w, wB.x, wB.y, wB.z, wB.w};
            #pragma unroll
            for (int fi = 0; fi < 8; fi++) {
                float2 s = make_float2(wv[fi], wv[fi]);
                acc[fi][0] = ffma2(s, p0, acc[fi][0]);
                acc[fi][1] = ffma2(s, p1, acc[fi][1]);
                acc[fi][2] = ffma2(s, p2, acc[fi][2]);
                acc[fi][3] = ffma2(s, p3, acc[fi][3]);
            }
        }

        // ---- store filter-interleaved: yil2[p][t] = (y_even[t], y_odd[t]) ----
        #pragma unroll
        for (int pi = 0; pi < 4; pi++) {
            const int p = 4 * warp + pi;
            float2* yr = yil2 + p * YIL2S;
            #pragma unroll
            for (int j = 0; j < 4; j++) {
                int t = (j < 2) ? (tA + 2 * j) : (tA + 128 + 2 * (j - 2));
                float2 e = acc[2 * pi][j], o = acc[2 * pi + 1][j];
                yr[t]     = make_float2(e.x, o.x);
                yr[t + 1] = make_float2(e.y, o.y);
            }
        }
        __syncthreads();

        // ---- stage interleaved conv weights: cw2[p][k] = (cw[2p][k], cw[2p+1][k]) ----
        #pragma unroll
        for (int r = 0; r < 16; r++) {
            int idx = r * 256 + tid;
            int f = idx >> 6, k = idx & 63;
            float v = conv_w[(gbase + f) * K_ + k];
            ((float*)cw2)[(f >> 1) * (2 * CW2S) + 2 * k + (f & 1)] = v;
        }
        __syncthreads();

        // ---- temporal conv: pair = lane, slot = warp (24 t = 2 chunks of 12) ----
        const float2* yr  = yil2 + lane * YIL2S;
        const float2* cwr = cw2 + lane * CW2S;
        float pe = 0.f, po = 0.f;

        #pragma unroll
        for (int ch = 0; ch < 2; ch++) {
            const int t0 = 24 * warp + 12 * ch;

            float2 tacc[12];
            #pragma unroll
            for (int i = 0; i < 12; i++) tacc[i] = make_float2(0.f, 0.f);

            float2 w2[16];
            #pragma unroll
            for (int i = 0; i < 16; i++) w2[i] = yr[t0 + i];

            for (int ko = 0; ko < 4; ko++) {       // 4 x 16 k-steps
                #pragma unroll
                for (int ku = 0; ku < 16; ku++) {
                    const int k = 16 * ko + ku;
                    float2 s = cwr[k];
                    #pragma unroll
                    for (int i = 0; i < 12; i++)
                        tacc[i] = ffma2(s, w2[(ku + i) & 15], tacc[i]);
                    // maintain invariant: slot (k&15) <- y[t0+k+16]
                    // (over-reads up to yr[t0+79] <= index 260: inside padded row)
                    w2[ku] = yr[t0 + k + 16];
                }
            }

            #pragma unroll
            for (int i = 0; i < 12; i++) {
                float iv = invn[t0 + i];   // 0 kills t >= TOUT and padding
                pe += fabsf(tacc[i].x) * iv;
                po += fabsf(tacc[i].y) * iv;
            }
        }

        atomicAdd(&g_acc[b * F_ + gbase + 2 * lane],     pe);
        atomicAdd(&g_acc[b * F_ + gbase + 2 * lane + 1], po);
    }

    // ---- last-CTA finish: apply per-filter weight factors + bias; reset ----
    __threadfence();
    __syncthreads();
    if (tid == 0) {
        unsigned old = atomicAdd(&g_count, 1u);
        sflag = (old == NCTA_ - 1) ? 1u : 0u;
    }
    __syncthreads();
    if (sflag) {
        float* wf_s = sm;   // reuse smem
        if (tid < F_) {
            int f = tid;
            float sc = 0.f, ss = 0.f;
            #pragma unroll 8
            for (int k = 0; k < K_; k++) { float v = conv_w[f * K_ + k]; sc += v * v; }
            #pragma unroll 8
            for (int c = 0; c < CIN_; c++) { float v = spat_w[f * CIN_ + c]; ss += v * v; }
            // scale = sqrt(CIN*K) = 64 exactly; fold 1/Tout for the mean
            wf_s[f] = weight[f] * 64.0f / (sqrtf(sc) * sqrtf(ss) * (float)TOUT_);
        }
        __syncthreads();
        if (tid < B_) {
            float s = 0.f;
            #pragma unroll 8
            for (int f = 0; f < F_; f++)
                s += bias[f] + wf_s[f] * __ldcg(&g_acc[tid * F_ + f]);
            out[tid] = s;
        }
        __syncthreads();
        for (int i = tid; i < B_ * F_; i += 256) g_acc[i] = 0.f;
        if (tid == 0) g_count = 0u;
    }
}

// ---------------------------------------------------------------------------
extern "C" void kernel_launch(void* const* d_in, const int* in_sizes, int n_in,
                              void* d_out, int out_size) {
    const float* x      = (const float*)d_in[0];  // [64,64,4096]
    const float* conv_w = (const float*)d_in[1];  // [128,64]
    const float* spat_w = (const float*)d_in[2];  // [128,64]
    const float* weight = (const float*)d_in[3];  // [128]
    const float* bias   = (const float*)d_in[4];  // [128]
    float* out = (float*)d_out;                   // [64]

    cudaFuncSetAttribute(main_kernel,
                         cudaFuncAttributeMaxDynamicSharedMemorySize,
                         SMEM_FLOATS * sizeof(float));

    dim3 grid(NT_, B_);
    main_kernel<<<grid, 256, SMEM_FLOATS * sizeof(float)>>>(
        x, conv_w, spat_w, weight, bias, out);
}

// round 6
// speedup vs baseline: 1.0546x; 1.0485x over previous
#include <cuda_runtime.h>
#include <cstdint>

// Problem constants
#define B_    64
#define CIN_  64
#define T_    4096
#define F_    128
#define K_    64
#define TOUT_ 4033          // T - K + 1
#define TILE_ 128           // conv outputs per CTA tile
#define SPAN_ 192           // TILE_ + K_ (y values per tile)
#define NT_   32            // ceil(TOUT_/TILE_)
#define NCTA_ (NT_ * B_)    // 2048

#define YIL2S 195           // yil row stride in float2 (odd, mod16=3 -> conflict-free)
#define CW2S  65            // cwil row stride in float2 (odd)
#define SPS   68            // spatT row stride (floats, mult of 4 for LDS.128)

// smem layout (floats)
#define OFF_YIL  0                       // 32 * 195 * 2 = 12480
#define OFF_U    12480                   // max(spatT 64*68=4352, cwil 32*65*2=4160)
#define OFF_SSQ  (OFF_U + 4352)          // 192 (+pad)
#define OFF_INV  (OFF_SSQ + 200)         // 128 (+pad)
#define SMEM_FLOATS (OFF_INV + 136)      // 17168 floats = 68672 B -> 3 CTAs/SM

__device__ float    g_acc[B_ * F_];      // deferred per-(b,f) sums (zero-init)
__device__ unsigned g_count;             // CTA completion counter (zero-init)

// ---------------------------------------------------------------------------
// Packed f32x2 FMA (SASS FFMA2 — only reachable via PTX)
// ---------------------------------------------------------------------------
__device__ __forceinline__ float2 ffma2(float2 a, float2 b, float2 c) {
    union U { float2 f; unsigned long long u; };
    U ua{a}, ub{b}, uc{c}, ur;
    asm("fma.rn.f32x2 %0, %1, %2, %3;" : "=l"(ur.u) : "l"(ua.u), "l"(ub.u), "l"(uc.u));
    return ur.f;
}

// ---------------------------------------------------------------------------
// Single fused kernel: one CTA per (t-tile, batch); last CTA finishes.
// ---------------------------------------------------------------------------
__global__ __launch_bounds__(256, 3)
void main_kernel(const float* __restrict__ x,
                 const float* __restrict__ conv_w,
                 const float* __restrict__ spat_w,
                 const float* __restrict__ weight,
                 const float* __restrict__ bias,
                 float* __restrict__ out) {
    extern __shared__ float sm[];
    float2* yil2 = (float2*)(sm + OFF_YIL);   // [32 pairs][YIL2S f2]
    float*  un   = sm + OFF_U;                // spatT / cwil union
    float2* cw2  = (float2*)(sm + OFF_U);
    float*  ssq  = sm + OFF_SSQ;              // [192]
    float*  invn = sm + OFF_INV;              // [128]
    __shared__ unsigned sflag;

    const int tid  = threadIdx.x;
    const int b    = blockIdx.y;
    const int tile = blockIdx.x;
    const int t0g  = tile * TILE_;
    const int warp = tid >> 5;
    const int lane = tid & 31;

    const float* xb = x + (size_t)b * CIN_ * T_;

    // ---- channel-energy ssq[t], t in [t0g, t0g+SPAN) ----
    if (tid < SPAN_) {
        int t = t0g + tid;
        float s = 0.f;
        if (t < T_) {
            #pragma unroll 8
            for (int c = 0; c < CIN_; c++) { float v = xb[c * T_ + t]; s += v * v; }
        }
        ssq[tid] = s;
    }
    __syncthreads();
    if (tid < TILE_) {
        float s = 0.f;
        #pragma unroll 8
        for (int k = 0; k < K_; k++) s += ssq[tid + k];
        invn[tid] = ((t0g + tid) < TOUT_ && s > 0.f) ? rsqrtf(s) : 0.f;
    }

    // spatial mapping: warp -> 8 filters; lane -> t = {4L..4L+3} and {128+2L, +1}
    const int fo = 8 * warp;
    const int tA = 4 * lane;
    const int tB = 128 + 2 * lane;
    // Q1 never OOB (t0g+127 <= 4095). Q2 valid iff whole tile span < T_ (uniform).
    const bool ok1 = (t0g + SPAN_ - 1) < T_;
    const float* xg = xb + t0g;
    const float2 z2 = make_float2(0.f, 0.f);

    for (int g = 0; g < 2; g++) {
        const int gbase = 64 * g;

        // ---- stage spatT: un[c*SPS + f] = spat_w[(gbase+f)*64 + c] ----
        __syncthreads();
        #pragma unroll
        for (int r = 0; r < 16; r++) {
            int idx = r * 256 + tid;
            int f = idx >> 6, c = idx & 63;
            un[c * SPS + f] = spat_w[(gbase + f) * CIN_ + c];
        }
        __syncthreads();

        // ---- spatial GEMM: 8 filters x 6 t per thread, x prefetched (L1) ----
        float2 acc[8][3];
        #pragma unroll
        for (int fi = 0; fi < 8; fi++)
            #pragma unroll
            for (int j = 0; j < 3; j++) acc[fi][j] = make_float2(0.f, 0.f);

        const float* xc0 = xg + tA;
        const float* xc1 = xg + tB;
        float4 xa = *(const float4*)(xc0);
        float2 xv = ok1 ? *(const float2*)(xc1) : z2;

        #pragma unroll 4
        for (int c = 0; c < CIN_; c++) {
            float4 xa_c = xa;
            float2 xv_c = xv;
            if (c + 1 < CIN_) {
                xa = *(const float4*)(xc0 + (c + 1) * T_);
                xv = ok1 ? *(const float2*)(xc1 + (c + 1) * T_) : z2;
            }
            float4 wA = *(const float4*)(un + c * SPS + fo);
            float4 wB = *(const float4*)(un + c * SPS + fo + 4);
            float2 p0 = make_float2(xa_c.x, xa_c.y);
            float2 p1 = make_float2(xa_c.z, xa_c.w);
            float wv[8] = {wA.x, wA.y, wA.z, wA.w, wB.x, wB.y, wB.z, wB.w};
            #pragma unroll
            for (int fi = 0; fi < 8; fi++) {
                float2 s = make_float2(wv[fi], wv[fi]);
                acc[fi][0] = ffma2(s, p0,   acc[fi][0]);
                acc[fi][1] = ffma2(s, p1,   acc[fi][1]);
                acc[fi][2] = ffma2(s, xv_c, acc[fi][2]);
            }
        }

        // ---- store filter-interleaved y: yil2[p][t] = (y_even[t], y_odd[t]) ----
        #pragma unroll
        for (int pi = 0; pi < 4; pi++) {
            const int p = 4 * warp + pi;
            float2* yr = yil2 + p * YIL2S;
            float2 e0 = acc[2 * pi][0], o0 = acc[2 * pi + 1][0];
            float2 e1 = acc[2 * pi][1], o1 = acc[2 * pi + 1][1];
            float2 e2 = acc[2 * pi][2], o2 = acc[2 * pi + 1][2];
            yr[tA]     = make_float2(e0.x, o0.x);
            yr[tA + 1] = make_float2(e0.y, o0.y);
            yr[tA + 2] = make_float2(e1.x, o1.x);
            yr[tA + 3] = make_float2(e1.y, o1.y);
            yr[tB]     = make_float2(e2.x, o2.x);
            yr[tB + 1] = make_float2(e2.y, o2.y);
        }
        __syncthreads();

        // ---- stage interleaved conv weights: cw2[p][k] = (cw[2p][k], cw[2p+1][k])
        #pragma unroll
        for (int r = 0; r < 16; r++) {
            int idx = r * 256 + tid;
            int f = idx >> 6, k = idx & 63;
            float v = conv_w[(gbase + f) * K_ + k];
            ((float*)cw2)[(f >> 1) * (2 * CW2S) + 2 * k + (f & 1)] = v;
        }
        __syncthreads();

        // ---- temporal conv: pair = lane; warp -> 16 t (2 chunks of 8) ----
        const float2* yr  = yil2 + lane * YIL2S;
        const float2* cwr = cw2 + lane * CW2S;
        float pe = 0.f, po = 0.f;

        #pragma unroll
        for (int ch = 0; ch < 2; ch++) {
            const int t0 = 16 * warp + 8 * ch;

            float2 tacc[8];
            #pragma unroll
            for (int i = 0; i < 8; i++) tacc[i] = make_float2(0.f, 0.f);

            float2 w2[8];          // modular window: holds y[t0+k .. t0+k+7]
            #pragma unroll
            for (int i = 0; i < 8; i++) w2[i] = yr[t0 + i];

            for (int ko = 0; ko < 8; ko++) {       // 8 x 8 k-steps
                #pragma unroll
                for (int ku = 0; ku < 8; ku++) {
                    const int k = 8 * ko + ku;
                    float2 s = cwr[k];
                    #pragma unroll
                    for (int i = 0; i < 8; i++)
                        tacc[i] = ffma2(s, w2[(ku + i) & 7], tacc[i]);
                    // refill invariant: slot (k&7) <- y[t0+k+8] (max idx 191 < 195)
                    w2[ku] = yr[t0 + k + 8];
                }
            }

            #pragma unroll
            for (int i = 0; i < 8; i++) {
                float iv = invn[t0 + i];   // 0 kills t >= TOUT and padding
                pe += fabsf(tacc[i].x) * iv;
                po += fabsf(tacc[i].y) * iv;
            }
        }

        atomicAdd(&g_acc[b * F_ + gbase + 2 * lane],     pe);
        atomicAdd(&g_acc[b * F_ + gbase + 2 * lane + 1], po);
    }

    // ---- last-CTA finish: apply per-filter weight factors + bias; reset ----
    __threadfence();
    __syncthreads();
    if (tid == 0) {
        unsigned old = atomicAdd(&g_count, 1u);
        sflag = (old == NCTA_ - 1) ? 1u : 0u;
    }
    __syncthreads();
    if (sflag) {
        float* wf_s = sm;   // reuse smem
        if (tid < F_) {
            int f = tid;
            float sc = 0.f, ss = 0.f;
            #pragma unroll 8
            for (int k = 0; k < K_; k++) { float v = conv_w[f * K_ + k]; sc += v * v; }
            #pragma unroll 8
            for (int c = 0; c < CIN_; c++) { float v = spat_w[f * CIN_ + c]; ss += v * v; }
            // scale = sqrt(CIN*K) = 64 exactly; fold 1/Tout for the mean
            wf_s[f] = weight[f] * 64.0f / (sqrtf(sc) * sqrtf(ss) * (float)TOUT_);
        }
        __syncthreads();
        if (tid < B_) {
            float s = 0.f;
            #pragma unroll 8
            for (int f = 0; f < F_; f++)
                s += bias[f] + wf_s[f] * __ldcg(&g_acc[tid * F_ + f]);
            out[tid] = s;
        }
        __syncthreads();
        for (int i = tid; i < B_ * F_; i += 256) g_acc[i] = 0.f;
        if (tid == 0) g_count = 0u;
    }
}

// ---------------------------------------------------------------------------
extern "C" void kernel_launch(void* const* d_in, const int* in_sizes, int n_in,
                              void* d_out, int out_size) {
    const float* x      = (const float*)d_in[0];  // [64,64,4096]
    const float* conv_w = (const float*)d_in[1];  // [128,64]
    const float* spat_w = (const float*)d_in[2];  // [128,64]
    const float* weight = (const float*)d_in[3];  // [128]
    const float* bias   = (const float*)d_in[4];  // [128]
    float* out = (float*)d_out;                   // [64]

    cudaFuncSetAttribute(main_kernel,
                         cudaFuncAttributeMaxDynamicSharedMemorySize,
                         SMEM_FLOATS * sizeof(float));

    dim3 grid(NT_, B_);
    main_kernel<<<grid, 256, SMEM_FLOATS * sizeof(float)>>>(
        x, conv_w, spat_w, weight, bias, out);
}

// round 7
// speedup vs baseline: 1.1744x; 1.1136x over previous
#include <cuda_runtime.h>
#include <cstdint>

// Problem constants
#define B_    64
#define CIN_  64
#define T_    4096
#define F_    128
#define K_    64
#define TOUT_ 4033          // T - K + 1
#define TILE_ 128           // conv outputs per CTA tile
#define SPAN_ 192           // TILE_ + K_ (y values per tile)
#define NT_   32            // ceil(TOUT_/TILE_)
#define NCTA_ (NT_ * B_)    // 2048

#define YIL2S 193           // yil row stride (float2): word-stride 386 % 32 == 2 -> conflict-free
#define CW2S  65            // cwil row stride (float2): word-stride 130 % 32 == 2 -> conflict-free
#define SPS   68            // spatT row stride (floats, mult of 4 for LDS.128)

// smem layout (floats)
#define OFF_YIL  0                       // 32 * 193 * 2 = 12352
#define OFF_U    12352                   // max(spatT 64*68=4352, cwil 32*130=4160)
#define OFF_SSQ  (OFF_U + 4352)          // 192 (+pad)
#define OFF_INV  (OFF_SSQ + 200)         // 128 (+pad)
#define OFF_SACC (OFF_INV + 136)         // 128
#define SMEM_FLOATS (OFF_SACC + 128)     // 17168 floats = 68672 B -> 3 CTAs/SM

__device__ float    g_acc[B_ * F_];      // deferred per-(b,f) sums (zero-init)
__device__ unsigned g_count;             // CTA completion counter (zero-init)

// ---------------------------------------------------------------------------
// Packed f32x2 FMA (SASS FFMA2 — only reachable via PTX)
// ---------------------------------------------------------------------------
__device__ __forceinline__ float2 ffma2(float2 a, float2 b, float2 c) {
    union U { float2 f; unsigned long long u; };
    U ua{a}, ub{b}, uc{c}, ur;
    asm("fma.rn.f32x2 %0, %1, %2, %3;" : "=l"(ur.u) : "l"(ua.u), "l"(ub.u), "l"(uc.u));
    return ur.f;
}

// ---------------------------------------------------------------------------
// Single fused kernel: one CTA per (t-tile, batch); last CTA finishes.
// ---------------------------------------------------------------------------
__global__ __launch_bounds__(256, 3)
void main_kernel(const float* __restrict__ x,
                 const float* __restrict__ conv_w,
                 const float* __restrict__ spat_w,
                 const float* __restrict__ weight,
                 const float* __restrict__ bias,
                 float* __restrict__ out) {
    extern __shared__ float sm[];
    float2* yil2 = (float2*)(sm + OFF_YIL);   // [32 pairs][YIL2S f2]
    float*  un   = sm + OFF_U;                // spatT / cwil union
    float2* cw2  = (float2*)(sm + OFF_U);
    float*  ssq  = sm + OFF_SSQ;              // [192]
    float*  invn = sm + OFF_INV;              // [128]
    float*  sacc = sm + OFF_SACC;             // [128] per-CTA filter sums
    __shared__ unsigned sflag;

    const int tid  = threadIdx.x;
    const int b    = blockIdx.y;
    const int tile = blockIdx.x;
    const int t0g  = tile * TILE_;
    const int warp = tid >> 5;
    const int lane = tid & 31;

    const float* xb = x + (size_t)b * CIN_ * T_;

    if (tid < F_) sacc[tid] = 0.f;

    // ---- channel-energy ssq[t], t in [t0g, t0g+SPAN) ----
    if (tid < SPAN_) {
        int t = t0g + tid;
        float s = 0.f;
        if (t < T_) {
            #pragma unroll 8
            for (int c = 0; c < CIN_; c++) { float v = xb[c * T_ + t]; s += v * v; }
        }
        ssq[tid] = s;
    }
    __syncthreads();
    if (tid < TILE_) {
        float s = 0.f;
        #pragma unroll 8
        for (int k = 0; k < K_; k++) s += ssq[tid + k];
        invn[tid] = ((t0g + tid) < TOUT_ && s > 0.f) ? rsqrtf(s) : 0.f;
    }

    // spatial 2-D warp grid: 4 filter-groups x 2 t-halves
    const int wf4   = warp & 3;          // filter group: 16 filters
    const int wt    = warp >> 2;         // t half: 96 t
    const int f0    = 16 * wf4;
    const int tbase = 96 * wt;
    const int tt    = lane & 7;          // 8 t-columns
    const int fr    = lane >> 3;         // 4 filter-rows
    const int fth   = f0 + 4 * fr;       // thread's first filter (even)

    // x quad offsets (local), clamped so loads never fault; garbage y is
    // confined to local t>=128 of the last tile, killed by invn==0.
    const int omax = T_ - 4 - t0g;       // >= 124 for all tiles
    const int oq0r = tbase + 4 * tt;
    const int o0 = min(oq0r,      omax);
    const int o1 = min(oq0r + 32, omax);
    const int o2 = min(oq0r + 64, omax);
    const float* xg = xb + t0g;

    // temporal mapping: pair = lane; warp -> 16 t
    const int t0c = 16 * warp;

    for (int g = 0; g < 2; g++) {
        const int gbase = 64 * g;

        // ---- stage spatT: un[c*SPS + f] = spat_w[(gbase+f)*64 + c] ----
        __syncthreads();
        #pragma unroll
        for (int r = 0; r < 16; r++) {
            int idx = r * 256 + tid;
            int f = idx >> 6, c = idx & 63;
            un[c * SPS + f] = spat_w[(gbase + f) * CIN_ + c];
        }
        __syncthreads();

        // ---- spatial GEMM: 4 filters x 12 t per thread ----
        float2 acc[4][6];
        #pragma unroll
        for (int fi = 0; fi < 4; fi++)
            #pragma unroll
            for (int j = 0; j < 6; j++) acc[fi][j] = make_float2(0.f, 0.f);

        #pragma unroll 2
        for (int c = 0; c < CIN_; c++) {
            float4 x0 = *(const float4*)(xg + c * T_ + o0);
            float4 x1 = *(const float4*)(xg + c * T_ + o1);
            float4 x2 = *(const float4*)(xg + c * T_ + o2);
            float4 w4 = *(const float4*)(un + c * SPS + fth);
            float2 xp[6] = { make_float2(x0.x, x0.y), make_float2(x0.z, x0.w),
                             make_float2(x1.x, x1.y), make_float2(x1.z, x1.w),
                             make_float2(x2.x, x2.y), make_float2(x2.z, x2.w) };
            float wv[4] = { w4.x, w4.y, w4.z, w4.w };
            #pragma unroll
            for (int fi = 0; fi < 4; fi++) {
                float2 s = make_float2(wv[fi], wv[fi]);
                #pragma unroll
                for (int j = 0; j < 6; j++)
                    acc[fi][j] = ffma2(s, xp[j], acc[fi][j]);
            }
        }

        // ---- store filter-interleaved y: yil2[p][t] = (y_even[t], y_odd[t]) ----
        {
            const int p0 = fth >> 1;     // thread's first pair (of 2)
            #pragma unroll
            for (int pi = 0; pi < 2; pi++) {
                float2* yr = yil2 + (p0 + pi) * YIL2S;
                const int fa = 2 * pi, fb = 2 * pi + 1;
                #pragma unroll
                for (int q = 0; q < 3; q++) {
                    const int tq = oq0r + 32 * q;    // real local t (unclamped)
                    float2 ea = acc[fa][2 * q],     eb = acc[fb][2 * q];
                    float2 ca = acc[fa][2 * q + 1], cb = acc[fb][2 * q + 1];
                    yr[tq]     = make_float2(ea.x, eb.x);
                    yr[tq + 1] = make_float2(ea.y, eb.y);
                    yr[tq + 2] = make_float2(ca.x, cb.x);
                    yr[tq + 3] = make_float2(ca.y, cb.y);
                }
            }
        }
        __syncthreads();

        // ---- stage interleaved conv weights: cw2[p][k] = (cw[2p][k], cw[2p+1][k])
        #pragma unroll
        for (int r = 0; r < 16; r++) {
            int idx = r * 256 + tid;
            int f = idx >> 6, k = idx & 63;
            float v = conv_w[(gbase + f) * K_ + k];
            ((float*)cw2)[(f >> 1) * (2 * CW2S) + 2 * k + (f & 1)] = v;
        }
        __syncthreads();

        // ---- temporal conv: 16 t per warp, modular 16-slot window ----
        {
            const float2* yr  = yil2 + lane * YIL2S;
            const float2* cwr = cw2 + lane * CW2S;

            float2 tacc[16];
            #pragma unroll
            for (int i = 0; i < 16; i++) tacc[i] = make_float2(0.f, 0.f);

            float2 w2[16];
            #pragma unroll
            for (int i = 0; i < 16; i++) w2[i] = yr[t0c + i];

            for (int ko = 0; ko < 4; ko++) {
                #pragma unroll
                for (int ku = 0; ku < 16; ku++) {
                    const int k = 16 * ko + ku;
                    float2 s = cwr[k];
                    #pragma unroll
                    for (int i = 0; i < 16; i++)
                        tacc[i] = ffma2(s, w2[(ku + i) & 15], tacc[i]);
                    // refill: slot (k&15) <- y[t0c+k+16]  (max idx 191 < 193)
                    w2[ku] = yr[t0c + k + 16];
                }
            }

            float pe = 0.f, po = 0.f;
            #pragma unroll
            for (int i = 0; i < 16; i++) {
                float iv = invn[t0c + i];   // 0 kills t >= TOUT and garbage-y region
                pe += fabsf(tacc[i].x) * iv;
                po += fabsf(tacc[i].y) * iv;
            }
            atomicAdd(&sacc[gbase + 2 * lane],     pe);
            atomicAdd(&sacc[gbase + 2 * lane + 1], po);
        }
    }

    // ---- one gmem atomic per filter ----
    __syncthreads();
    if (tid < F_) atomicAdd(&g_acc[b * F_ + tid], sacc[tid]);

    // ---- last-CTA finish: apply per-filter weight factors + bias; reset ----
    __threadfence();
    __syncthreads();
    if (tid == 0) {
        unsigned old = atomicAdd(&g_count, 1u);
        sflag = (old == NCTA_ - 1) ? 1u : 0u;
    }
    __syncthreads();
    if (sflag) {
        float* wf_s = sm;   // reuse smem
        if (tid < F_) {
            int f = tid;
            float sc = 0.f, ss = 0.f;
            #pragma unroll 8
            for (int k = 0; k < K_; k++) { float v = conv_w[f * K_ + k]; sc += v * v; }
            #pragma unroll 8
            for (int c = 0; c < CIN_; c++) { float v = spat_w[f * CIN_ + c]; ss += v * v; }
            // scale = sqrt(CIN*K) = 64 exactly; fold 1/Tout for the mean
            wf_s[f] = weight[f] * 64.0f / (sqrtf(sc) * sqrtf(ss) * (float)TOUT_);
        }
        __syncthreads();
        if (tid < B_) {
            float s = 0.f;
            #pragma unroll 8
            for (int f = 0; f < F_; f++)
                s += bias[f] + wf_s[f] * __ldcg(&g_acc[tid * F_ + f]);
            out[tid] = s;
        }
        __syncthreads();
        for (int i = tid; i < B_ * F_; i += 256) g_acc[i] = 0.f;
        if (tid == 0) g_count = 0u;
    }
}

// ---------------------------------------------------------------------------
extern "C" void kernel_launch(void* const* d_in, const int* in_sizes, int n_in,
                              void* d_out, int out_size) {
    const float* x      = (const float*)d_in[0];  // [64,64,4096]
    const float* conv_w = (const float*)d_in[1];  // [128,64]
    const float* spat_w = (const float*)d_in[2];  // [128,64]
    const float* weight = (const float*)d_in[3];  // [128]
    const float* bias   = (const float*)d_in[4];  // [128]
    float* out = (float*)d_out;                   // [64]

    cudaFuncSetAttribute(main_kernel,
                         cudaFuncAttributeMaxDynamicSharedMemorySize,
                         SMEM_FLOATS * sizeof(float));

    dim3 grid(NT_, B_);
    main_kernel<<<grid, 256, SMEM_FLOATS * sizeof(float)>>>(
        x, conv_w, spat_w, weight, bias, out);
}

// round 8
// speedup vs baseline: 1.1959x; 1.0183x over previous
#include <cuda_runtime.h>
#include <cstdint>

// Problem constants
#define B_    64
#define CIN_  64
#define T_    4096
#define F_    128
#define K_    64
#define TOUT_ 4033          // T - K + 1
#define TILE_ 128           // conv outputs per CTA tile
#define SPAN_ 192           // TILE_ + K_ (y values per tile)
#define NT_   32            // ceil(TOUT_/TILE_)
#define NCTA_ (NT_ * B_)    // 2048

#define XS_   192           // x_s row stride (floats); lanes vary t only -> conflict-free
#define YIL2S 193           // yil row stride (float2): lane word-stride 386 % 32 == 2 -> CF
#define CW2S  65            // cwil row stride (float2): word-stride 130 % 32 == 2 -> CF
#define SPS   68            // spatT row stride (floats, mult of 4 for LDS.128)

// smem layout (floats)
#define OFF_X    0                       // 32 * 192 = 6144 (one 32-channel chunk)
#define OFF_YIL  6144                    // 32 * 193 * 2 = 12352
#define OFF_U    (6144 + 12352)          // max(spatT 64*68=4352, cwil 32*130=4160)
#define OFF_SSQ  (OFF_U + 4352)          // 192 (+pad)
#define OFF_INV  (OFF_SSQ + 200)         // 128 (+pad)
#define OFF_SACC (OFF_INV + 136)         // 128
#define SMEM_FLOATS (OFF_SACC + 128)     // 23312 floats = 93248 B -> 2 CTAs/SM

__device__ float    g_acc[B_ * F_];      // deferred per-(b,f) sums (zero-init)
__device__ unsigned g_count;             // CTA completion counter (zero-init)

// ---------------------------------------------------------------------------
// Packed f32x2 FMA (SASS FFMA2 — only reachable via PTX)
// ---------------------------------------------------------------------------
__device__ __forceinline__ float2 ffma2(float2 a, float2 b, float2 c) {
    union U { float2 f; unsigned long long u; };
    U ua{a}, ub{b}, uc{c}, ur;
    asm("fma.rn.f32x2 %0, %1, %2, %3;" : "=l"(ur.u) : "l"(ua.u), "l"(ub.u), "l"(uc.u));
    return ur.f;
}

// ---------------------------------------------------------------------------
// Single fused kernel: one CTA per (t-tile, batch); last CTA finishes.
// ---------------------------------------------------------------------------
__global__ __launch_bounds__(256, 2)
void main_kernel(const float* __restrict__ x,
                 const float* __restrict__ conv_w,
                 const float* __restrict__ spat_w,
                 const float* __restrict__ weight,
                 const float* __restrict__ bias,
                 float* __restrict__ out) {
    extern __shared__ float sm[];
    float*  x_s  = sm + OFF_X;                // [32 c][XS_]
    float2* yil2 = (float2*)(sm + OFF_YIL);   // [32 pairs][YIL2S f2]
    float*  un   = sm + OFF_U;                // spatT / cwil union
    float2* cw2  = (float2*)(sm + OFF_U);
    float*  ssq  = sm + OFF_SSQ;              // [192]
    float*  invn = sm + OFF_INV;              // [128]
    float*  sacc = sm + OFF_SACC;             // [128]
    __shared__ unsigned sflag;

    const int tid  = threadIdx.x;
    const int b    = blockIdx.y;
    const int tile = blockIdx.x;
    const int t0g  = tile * TILE_;
    const int warp = tid >> 5;
    const int lane = tid & 31;

    const float* xb = x + (size_t)b * CIN_ * T_;
    const float4 z4 = make_float4(0.f, 0.f, 0.f, 0.f);

    if (tid < F_) sacc[tid] = 0.f;
    if (tid < SPAN_) ssq[tid] = 0.f;

    // spatial 2-D warp grid: 4 filter-groups x 2 t-halves
    const int wf4   = warp & 3;          // 16 filters
    const int wt    = warp >> 2;         // 96-t half
    const int tbase = 96 * wt;
    const int tt    = lane & 7;          // 8 t-columns (quads)
    const int fr    = lane >> 3;         // 4 filter-rows
    const int fth   = 16 * wf4 + 4 * fr; // thread's first filter (even)
    const int tq0   = tbase + 4 * tt;

    // temporal mapping: pair = lane; warp -> 16 t
    const int t0c = 16 * warp;

    for (int g = 0; g < 2; g++) {
        const int gbase = 64 * g;

        float2 acc[4][6];
        #pragma unroll
        for (int fi = 0; fi < 4; fi++)
            #pragma unroll
            for (int j = 0; j < 6; j++) acc[fi][j] = make_float2(0.f, 0.f);

        #pragma unroll
        for (int cb = 0; cb < 2; cb++) {        // 32-channel chunks
            __syncthreads();   // x_s/un free of previous readers

            if (cb == 0) {
                // stage spatT: un[c*SPS + f] = spat_w[(gbase+f)*64 + c]
                #pragma unroll
                for (int r = 0; r < 16; r++) {
                    int idx = r * 256 + tid;
                    int f = idx >> 6, c = idx & 63;
                    un[c * SPS + f] = spat_w[(gbase + f) * CIN_ + c];
                }
            }
            // stage x chunk: 32 c x 192 t (quads fully in or out of range)
            #pragma unroll
            for (int r = 0; r < 6; r++) {
                int idx = r * 256 + tid;        // 0..1535
                int cc = idx / 48;
                int tl = (idx % 48) * 4;
                int tg = t0g + tl;
                float4 v = (tg + 3 < T_)
                    ? *(const float4*)(xb + (size_t)(32 * cb + cc) * T_ + tg) : z4;
                *(float4*)(x_s + cc * XS_ + tl) = v;
            }
            __syncthreads();

            // ssq partials (only first group; x identical across groups)
            if (g == 0 && tid < SPAN_) {
                float s = 0.f;
                #pragma unroll 8
                for (int cc = 0; cc < 32; cc++) {
                    float v = x_s[cc * XS_ + tid];
                    s += v * v;
                }
                ssq[tid] += s;
            }

            // spatial GEMM partial: 4 filters x 12 t per thread
            #pragma unroll 2
            for (int cc = 0; cc < 32; cc++) {
                const float* xr = x_s + cc * XS_ + tq0;
                float4 x0 = *(const float4*)(xr);
                float4 x1 = *(const float4*)(xr + 32);
                float4 x2 = *(const float4*)(xr + 64);
                float4 w4 = *(const float4*)(un + (32 * cb + cc) * SPS + fth);
                float2 xp[6] = { make_float2(x0.x, x0.y), make_float2(x0.z, x0.w),
                                 make_float2(x1.x, x1.y), make_float2(x1.z, x1.w),
                                 make_float2(x2.x, x2.y), make_float2(x2.z, x2.w) };
                float wv[4] = { w4.x, w4.y, w4.z, w4.w };
                #pragma unroll
                for (int fi = 0; fi < 4; fi++) {
                    float2 s = make_float2(wv[fi], wv[fi]);
                    #pragma unroll
                    for (int j = 0; j < 6; j++)
                        acc[fi][j] = ffma2(s, xp[j], acc[fi][j]);
                }
            }
        }

        // ---- store filter-interleaved y: yil2[p][t] = (y_even[t], y_odd[t]) ----
        {
            const int p0 = fth >> 1;
            #pragma unroll
            for (int pi = 0; pi < 2; pi++) {
                float2* yr = yil2 + (p0 + pi) * YIL2S;
                const int fa = 2 * pi, fb = 2 * pi + 1;
                #pragma unroll
                for (int q = 0; q < 3; q++) {
                    const int tq = tq0 + 32 * q;
                    float2 ea = acc[fa][2 * q],     eb = acc[fb][2 * q];
                    float2 ca = acc[fa][2 * q + 1], cb2 = acc[fb][2 * q + 1];
                    yr[tq]     = make_float2(ea.x, eb.x);
                    yr[tq + 1] = make_float2(ea.y, eb.y);
                    yr[tq + 2] = make_float2(ca.x, cb2.x);
                    yr[tq + 3] = make_float2(ca.y, cb2.y);
                }
            }
        }
        __syncthreads();   // yil complete; un/x_s reads done

        // ---- stage interleaved conv weights (aliases spatT) + invn ----
        #pragma unroll
        for (int r = 0; r < 16; r++) {
            int idx = r * 256 + tid;
            int f = idx >> 6, k = idx & 63;
            float v = conv_w[(gbase + f) * K_ + k];
            ((float*)cw2)[(f >> 1) * (2 * CW2S) + 2 * k + (f & 1)] = v;
        }
        if (g == 0 && tid < TILE_) {
            float s = 0.f;
            #pragma unroll 8
            for (int k = 0; k < K_; k++) s += ssq[tid + k];
            invn[tid] = ((t0g + tid) < TOUT_ && s > 0.f) ? rsqrtf(s) : 0.f;
        }
        __syncthreads();

        // ---- temporal conv: 16 t per warp, modular 16-slot window ----
        {
            const float2* yr  = yil2 + lane * YIL2S;
            const float2* cwr = cw2 + lane * CW2S;

            float2 tacc[16];
            #pragma unroll
            for (int i = 0; i < 16; i++) tacc[i] = make_float2(0.f, 0.f);

            float2 w2[16];
            #pragma unroll
            for (int i = 0; i < 16; i++) w2[i] = yr[t0c + i];

            for (int ko = 0; ko < 4; ko++) {
                #pragma unroll
                for (int ku = 0; ku < 16; ku++) {
                    const int k = 16 * ko + ku;
                    float2 s = cwr[k];
                    #pragma unroll
                    for (int i = 0; i < 16; i++)
                        tacc[i] = ffma2(s, w2[(ku + i) & 15], tacc[i]);
                    // refill: slot (k&15) <- y[t0c+k+16]  (max idx 191 < 193)
                    w2[ku] = yr[t0c + k + 16];
                }
            }

            float pe = 0.f, po = 0.f;
            #pragma unroll
            for (int i = 0; i < 16; i++) {
                float iv = invn[t0c + i];   // 0 kills t >= TOUT and padded region
                pe += fabsf(tacc[i].x) * iv;
                po += fabsf(tacc[i].y) * iv;
            }
            atomicAdd(&sacc[gbase + 2 * lane],     pe);
            atomicAdd(&sacc[gbase + 2 * lane + 1], po);
        }
    }

    // ---- one gmem atomic per filter ----
    __syncthreads();
    if (tid < F_) atomicAdd(&g_acc[b * F_ + tid], sacc[tid]);

    // ---- last-CTA finish: apply per-filter weight factors + bias; reset ----
    __threadfence();
    __syncthreads();
    if (tid == 0) {
        unsigned old = atomicAdd(&g_count, 1u);
        sflag = (old == NCTA_ - 1) ? 1u : 0u;
    }
    __syncthreads();
    if (sflag) {
        float* wf_s = sm;   // reuse smem
        if (tid < F_) {
            int f = tid;
            float sc = 0.f, ss = 0.f;
            #pragma unroll 8
            for (int k = 0; k < K_; k++) { float v = conv_w[f * K_ + k]; sc += v * v; }
            #pragma unroll 8
            for (int c = 0; c < CIN_; c++) { float v = spat_w[f * CIN_ + c]; ss += v * v; }
            // scale = sqrt(CIN*K) = 64 exactly; fold 1/Tout for the mean
            wf_s[f] = weight[f] * 64.0f / (sqrtf(sc) * sqrtf(ss) * (float)TOUT_);
        }
        __syncthreads();
        if (tid < B_) {
            float s = 0.f;
            #pragma unroll 8
            for (int f = 0; f < F_; f++)
                s += bias[f] + wf_s[f] * __ldcg(&g_acc[tid * F_ + f]);
            out[tid] = s;
        }
        __syncthreads();
        for (int i = tid; i < B_ * F_; i += 256) g_acc[i] = 0.f;
        if (tid == 0) g_count = 0u;
    }
}

// ---------------------------------------------------------------------------
extern "C" void kernel_launch(void* const* d_in, const int* in_sizes, int n_in,
                              void* d_out, int out_size) {
    const float* x      = (const float*)d_in[0];  // [64,64,4096]
    const float* conv_w = (const float*)d_in[1];  // [128,64]
    const float* spat_w = (const float*)d_in[2];  // [128,64]
    const float* weight = (const float*)d_in[3];  // [128]
    const float* bias   = (const float*)d_in[4];  // [128]
    float* out = (float*)d_out;                   // [64]

    cudaFuncSetAttribute(main_kernel,
                         cudaFuncAttributeMaxDynamicSharedMemorySize,
                         SMEM_FLOATS * sizeof(float));

    dim3 grid(NT_, B_);
    main_kernel<<<grid, 256, SMEM_FLOATS * sizeof(float)>>>(
        x, conv_w, spat_w, weight, bias, out);
}